// round 10
// baseline (speedup 1.0000x reference)
#include <cuda_runtime.h>
#include <cuda_bf16.h>
#include <mma.h>
#include <cstdint>

using namespace nvcuda;

// Problem constants
constexpr int B = 2, S = 2048, D = 1024, H = 16, HD = 64;
constexpr size_t NEL = (size_t)B * S * D;   // 4194304
constexpr size_t WEL = (size_t)D * D;       // 1048576

// ---------------- scratch arena ----------------
constexpr size_t OFF_IN_HI  = 0;
constexpr size_t OFF_IN_LO  = OFF_IN_HI  + 3 * NEL * 2;
constexpr size_t OFF_W_HI   = OFF_IN_LO  + 3 * NEL * 2;
constexpr size_t OFF_W_LO   = OFF_W_HI   + 4 * WEL * 2;
constexpr size_t OFF_QKV_HI = OFF_W_LO   + 4 * WEL * 2;
constexpr size_t OFF_QKV_LO = OFF_QKV_HI + 3 * NEL * 2;
constexpr size_t OFF_XH_HI  = OFF_QKV_LO + 3 * NEL * 2;
constexpr size_t OFF_XH_LO  = OFF_XH_HI  + NEL * 2;
constexpr size_t ARENA_BYTES = OFF_XH_LO + NEL * 2;

__device__ __align__(256) unsigned char g_arena[ARENA_BYTES];

#define CP_ASYNC16(dst, src) asm volatile("cp.async.cg.shared.global [%0], [%1], 16;\n" :: "r"(dst), "l"(src))
#define CP_COMMIT()  asm volatile("cp.async.commit_group;\n" ::: "memory")
#define CP_WAIT0()   asm volatile("cp.async.wait_group 0;\n" ::: "memory")
#define CP_WAIT1()   asm volatile("cp.async.wait_group 1;\n" ::: "memory")

// ---------------- split fp32 -> bf16 hi/lo ----------------
__global__ void split_kernel(const float* __restrict__ src,
                             size_t hi_off, size_t lo_off, int n)
{
    int i = blockIdx.x * blockDim.x + threadIdx.x;
    if (i >= n) return;
    __nv_bfloat16* hi = (__nv_bfloat16*)(g_arena + hi_off);
    __nv_bfloat16* lo = (__nv_bfloat16*)(g_arena + lo_off);
    float x = src[i];
    __nv_bfloat16 h = __float2bfloat16(x);
    hi[i] = h;
    lo[i] = __float2bfloat16(x - __bfloat162float(h));
}

// ---------------- GEMM v4 (R7): 128x128 CTA tile, 2-stage, warp tile 64x32 ---
constexpr int G_ARR = 128 * 40 * 2;
constexpr int G_STG = 4 * G_ARR;
constexpr int GEMM_SMEM = 2 * G_STG;         // 81920

__global__ __launch_bounds__(256, 2) void gemm_kernel(
    size_t ahi_off, size_t alo_off, size_t whi_off, size_t wlo_off,
    const float* __restrict__ bias,
    float* __restrict__ cext, size_t hi_off, size_t lo_off)
{
    const __nv_bfloat16* Ahi = (const __nv_bfloat16*)(g_arena + ahi_off);
    const __nv_bfloat16* Alo = (const __nv_bfloat16*)(g_arena + alo_off);
    const __nv_bfloat16* Whi = (const __nv_bfloat16*)(g_arena + whi_off);
    const __nv_bfloat16* Wlo = (const __nv_bfloat16*)(g_arena + wlo_off);

    extern __shared__ unsigned char smraw[];

    int m0 = blockIdx.y * 128, n0 = blockIdx.x * 128;
    int tid = threadIdx.x, wid = tid >> 5;
    int wm = wid & 1, wn = wid >> 1;          // warp tile 64(m) x 32(n)

    auto fill = [&](int st, int kt) {
        int k0 = kt * 32;
        __nv_bfloat16* Ah = (__nv_bfloat16*)(smraw + st * G_STG);
        __nv_bfloat16* Al = (__nv_bfloat16*)(smraw + st * G_STG + G_ARR);
        __nv_bfloat16* Bh = (__nv_bfloat16*)(smraw + st * G_STG + 2 * G_ARR);
        __nv_bfloat16* Bl = (__nv_bfloat16*)(smraw + st * G_STG + 3 * G_ARR);
#pragma unroll
        for (int i = 0; i < 2; i++) {
            int v = tid + 256 * i;
            int r = v >> 2, c = (v & 3) * 8;
            size_t ga = (size_t)(m0 + r) * D + k0 + c;
            size_t gb = (size_t)(n0 + r) * D + k0 + c;
            CP_ASYNC16((unsigned)__cvta_generic_to_shared(Ah + r * 40 + c), Ahi + ga);
            CP_ASYNC16((unsigned)__cvta_generic_to_shared(Al + r * 40 + c), Alo + ga);
            CP_ASYNC16((unsigned)__cvta_generic_to_shared(Bh + r * 40 + c), Whi + gb);
            CP_ASYNC16((unsigned)__cvta_generic_to_shared(Bl + r * 40 + c), Wlo + gb);
        }
    };

    wmma::fragment<wmma::accumulator, 16, 16, 16, float> acc[4][2];
#pragma unroll
    for (int i = 0; i < 4; i++)
#pragma unroll
        for (int j = 0; j < 2; j++) wmma::fill_fragment(acc[i][j], 0.0f);

    fill(0, 0); CP_COMMIT();
    for (int kt = 0; kt < 32; kt++) {
        if (kt < 31) fill((kt + 1) & 1, kt + 1);
        CP_COMMIT();
        CP_WAIT1();
        __syncthreads();
        int st = kt & 1;
        const __nv_bfloat16* Ah = (const __nv_bfloat16*)(smraw + st * G_STG);
        const __nv_bfloat16* Al = (const __nv_bfloat16*)(smraw + st * G_STG + G_ARR);
        const __nv_bfloat16* Bh = (const __nv_bfloat16*)(smraw + st * G_STG + 2 * G_ARR);
        const __nv_bfloat16* Bl = (const __nv_bfloat16*)(smraw + st * G_STG + 3 * G_ARR);
#pragma unroll
        for (int kk = 0; kk < 32; kk += 16) {
            wmma::fragment<wmma::matrix_a, 16, 16, 16, __nv_bfloat16, wmma::row_major> ah[4], al[4];
#pragma unroll
            for (int i = 0; i < 4; i++) {
                wmma::load_matrix_sync(ah[i], Ah + (wm * 64 + i * 16) * 40 + kk, 40);
                wmma::load_matrix_sync(al[i], Al + (wm * 64 + i * 16) * 40 + kk, 40);
            }
#pragma unroll
            for (int j = 0; j < 2; j++) {
                wmma::fragment<wmma::matrix_b, 16, 16, 16, __nv_bfloat16, wmma::col_major> bh, bl;
                wmma::load_matrix_sync(bh, Bh + (wn * 32 + j * 16) * 40 + kk, 40);
                wmma::load_matrix_sync(bl, Bl + (wn * 32 + j * 16) * 40 + kk, 40);
#pragma unroll
                for (int i = 0; i < 4; i++) {
                    wmma::mma_sync(acc[i][j], ah[i], bh, acc[i][j]);
                    wmma::mma_sync(acc[i][j], ah[i], bl, acc[i][j]);
                    wmma::mma_sync(acc[i][j], al[i], bh, acc[i][j]);
                }
            }
        }
        __syncthreads();
    }

    float* Cs = (float*)smraw;
    __nv_bfloat16* hi = (__nv_bfloat16*)(g_arena + hi_off);
    __nv_bfloat16* lo = (__nv_bfloat16*)(g_arena + lo_off);
#pragma unroll
    for (int half = 0; half < 2; half++) {
        __syncthreads();
        if (wm == half) {
#pragma unroll
            for (int i = 0; i < 4; i++)
#pragma unroll
                for (int j = 0; j < 2; j++)
                    wmma::store_matrix_sync(Cs + (i * 16) * 132 + wn * 32 + j * 16,
                                            acc[i][j], 132, wmma::mem_row_major);
        }
        __syncthreads();
#pragma unroll
        for (int i = 0; i < 32; i++) {
            int v = tid + 256 * i;
            int r = v >> 7, c = v & 127;
            float x = Cs[r * 132 + c] + bias[n0 + c];
            size_t g = (size_t)(m0 + half * 64 + r) * D + n0 + c;
            if (cext) {
                cext[g] = x;
            } else {
                __nv_bfloat16 h = __float2bfloat16(x);
                hi[g] = h;
                lo[g] = __float2bfloat16(x - __bfloat162float(h));
            }
        }
    }
}

// ---------------- fused attention: recompute variant (no staging round-trip) -
// Pass 1: K stream (double-buffered) -> S=QK^T/8 -> tsum += exp(s). NO gmem write.
// Merge sums -> 1/l.
// Pass 2: K+V streams (single-buffered, alternating prefetch) -> recompute S
// (bit-identical), write p=exp(s)*il ONCE (final attn), split p -> AV.
constexpr int A_Q   = 0;
constexpr int A_QL  = A_Q  + 64 * 72 * 2;
constexpr int A_KV  = A_QL + 64 * 72 * 2;        // 4 arrays of 64x72 bf16 = 36864 B
constexpr int A_ARR = 64 * 72 * 2;               // 9216
constexpr int A_S   = A_KV + 4 * A_ARR;          // Sm[64][68] f32
constexpr int A_PH  = A_S  + 64 * 68 * 4;
constexpr int A_PL  = A_PH + 64 * 72 * 2;
constexpr int A_L   = A_PL + 64 * 72 * 2;        // lrowinv[64]
constexpr int ATTN_SMEM = A_L + 64 * 4;          // ~92 KB -> 2 CTA/SM

__global__ __launch_bounds__(256) void attn_fused_kernel(
    size_t qhi_off, size_t qlo_off, size_t khi_off, size_t klo_off,
    size_t vhi_off, size_t vlo_off,
    const int* __restrict__ mask, float* __restrict__ attn,
    size_t xhhi_off, size_t xhlo_off)
{
    extern __shared__ unsigned char smraw[];
    __nv_bfloat16* Qh  = (__nv_bfloat16*)(smraw + A_Q);
    __nv_bfloat16* Ql  = (__nv_bfloat16*)(smraw + A_QL);
    float*         Sm  = (float*)(smraw + A_S);
    __nv_bfloat16* Ph  = (__nv_bfloat16*)(smraw + A_PH);
    __nv_bfloat16* Pl  = (__nv_bfloat16*)(smraw + A_PL);
    float*         lrowinv = (float*)(smraw + A_L);

    const __nv_bfloat16* Qhi = (const __nv_bfloat16*)(g_arena + qhi_off);
    const __nv_bfloat16* Qlo = (const __nv_bfloat16*)(g_arena + qlo_off);
    const __nv_bfloat16* Khi = (const __nv_bfloat16*)(g_arena + khi_off);
    const __nv_bfloat16* Klo = (const __nv_bfloat16*)(g_arena + klo_off);
    const __nv_bfloat16* Vhi = (const __nv_bfloat16*)(g_arena + vhi_off);
    const __nv_bfloat16* Vlo = (const __nv_bfloat16*)(g_arena + vlo_off);

    int bh = blockIdx.y;
    int b = bh >> 4, h = bh & 15;
    int q0 = blockIdx.x * 64;
    int tid = threadIdx.x, wid = tid >> 5, lane = tid & 31;
    int wm = wid & 1, wn = wid >> 1;

    // load one 64x64 hi/lo tile pair into smem slot (slot = 0..1, each 2 arrays)
    auto prefetch_pair = [&](int slot, const __nv_bfloat16* srch, const __nv_bfloat16* srcl, int kt) {
        size_t gbase = ((size_t)b * S + kt * 64) * D + h * HD;
        __nv_bfloat16* dsth = (__nv_bfloat16*)(smraw + A_KV + slot * 2 * A_ARR);
        __nv_bfloat16* dstl = dsth + 64 * 72;
#pragma unroll
        for (int i = 0; i < 2; i++) {
            int v = tid + 256 * i;
            int r = v >> 3, c = (v & 7) * 8;
            size_t g = gbase + (size_t)r * D + c;
            CP_ASYNC16((unsigned)__cvta_generic_to_shared(dsth + r * 72 + c), srch + g);
            CP_ASYNC16((unsigned)__cvta_generic_to_shared(dstl + r * 72 + c), srcl + g);
        }
    };

    // scores MMA from smem slot into Sm (scaled by 1/8)
    auto scores_mma = [&](int slot) {
        const __nv_bfloat16* Kh = (const __nv_bfloat16*)(smraw + A_KV + slot * 2 * A_ARR);
        const __nv_bfloat16* Kl = Kh + 64 * 72;
        wmma::fragment<wmma::accumulator, 16, 16, 16, float> acc[2];
        wmma::fill_fragment(acc[0], 0.0f);
        wmma::fill_fragment(acc[1], 0.0f);
#pragma unroll
        for (int kk = 0; kk < HD; kk += 16) {
            wmma::fragment<wmma::matrix_a, 16, 16, 16, __nv_bfloat16, wmma::row_major> ah[2], al[2];
            wmma::fragment<wmma::matrix_b, 16, 16, 16, __nv_bfloat16, wmma::col_major> bh_, bl_;
#pragma unroll
            for (int i = 0; i < 2; i++) {
                wmma::load_matrix_sync(ah[i], Qh + (wm * 32 + i * 16) * 72 + kk, 72);
                wmma::load_matrix_sync(al[i], Ql + (wm * 32 + i * 16) * 72 + kk, 72);
            }
            wmma::load_matrix_sync(bh_, Kh + (wn * 16) * 72 + kk, 72);
            wmma::load_matrix_sync(bl_, Kl + (wn * 16) * 72 + kk, 72);
#pragma unroll
            for (int i = 0; i < 2; i++) {
                wmma::mma_sync(acc[i], ah[i], bh_, acc[i]);
                wmma::mma_sync(acc[i], ah[i], bl_, acc[i]);
                wmma::mma_sync(acc[i], al[i], bh_, acc[i]);
            }
        }
#pragma unroll
        for (int i = 0; i < 2; i++) {
            for (int t = 0; t < acc[i].num_elements; t++) acc[i].x[t] *= 0.125f;
            wmma::store_matrix_sync(Sm + (wm * 32 + i * 16) * 68 + wn * 16, acc[i], 68, wmma::mem_row_major);
        }
    };

    size_t qbase = ((size_t)b * S + q0) * D + h * HD;
#pragma unroll
    for (int i = 0; i < 4; i++) {
        int v = tid + 256 * i;
        int r = v >> 4, c = (v & 15) * 4;
        *(uint2*)&Qh[r * 72 + c] = *(const uint2*)(Qhi + qbase + (size_t)r * D + c);
        *(uint2*)&Ql[r * 72 + c] = *(const uint2*)(Qlo + qbase + (size_t)r * D + c);
    }
    __syncthreads();

    // ---------- pass 1: stats only (no gmem writes) ----------
    float tsum[8];
#pragma unroll
    for (int i = 0; i < 8; i++) tsum[i] = 0.0f;

    prefetch_pair(0, Khi, Klo, 0);
    CP_COMMIT();
    for (int kt = 0; kt < 32; kt++) {
        if (kt < 31) prefetch_pair((kt + 1) & 1, Khi, Klo, kt + 1);
        CP_COMMIT();
        CP_WAIT1();
        __syncthreads();

        scores_mma(kt & 1);
        __syncthreads();

        int colb = kt * 64;
        const int* mk = mask + (size_t)b * S + colb;
        int mv0 = mk[lane], mv1 = mk[lane + 32];
#pragma unroll
        for (int r8 = 0; r8 < 8; r8++) {
            int row = wid * 8 + r8;
            float s0 = Sm[row * 68 + lane];        if (mv0 == 0) s0 = -1e9f;
            float s1 = Sm[row * 68 + lane + 32];   if (mv1 == 0) s1 = -1e9f;
            tsum[r8] += __expf(s0) + __expf(s1);
        }
        __syncthreads();
    }
    CP_WAIT0();   // drain any remaining prefetch before buffer reuse

    // merge row sums, store 1/l
#pragma unroll
    for (int r8 = 0; r8 < 8; r8++) {
        float s = tsum[r8];
#pragma unroll
        for (int o = 16; o; o >>= 1) s += __shfl_xor_sync(0xffffffffu, s, o);
        if (lane == 0) lrowinv[wid * 8 + r8] = 1.0f / s;
    }
    __syncthreads();

    // ---------- pass 2: recompute S, write final attn, AV ----------
    // slot 0 = K tile, slot 1 = V tile (single-buffered, alternating prefetch)
    wmma::fragment<wmma::accumulator, 16, 16, 16, float> accO[2];
    wmma::fill_fragment(accO[0], 0.0f);
    wmma::fill_fragment(accO[1], 0.0f);

    prefetch_pair(0, Khi, Klo, 0);
    CP_COMMIT();
    for (int kt = 0; kt < 32; kt++) {
        CP_WAIT0();          // K tile kt ready
        __syncthreads();
        prefetch_pair(1, Vhi, Vlo, kt);    // V prefetch overlaps scores MMA
        CP_COMMIT();

        scores_mma(0);
        __syncthreads();

        int colb = kt * 64;
        const int* mk = mask + (size_t)b * S + colb;
        int mv0 = mk[lane], mv1 = mk[lane + 32];
#pragma unroll
        for (int r8 = 0; r8 < 8; r8++) {
            int row = wid * 8 + r8;
            float il = lrowinv[row];
            float s0 = Sm[row * 68 + lane];        if (mv0 == 0) s0 = -1e9f;
            float s1 = Sm[row * 68 + lane + 32];   if (mv1 == 0) s1 = -1e9f;
            float p0 = __expf(s0) * il;
            float p1 = __expf(s1) * il;
            float* arow = attn + ((size_t)bh * S + q0 + row) * S + colb;
            arow[lane] = p0;                       // single, final attn write
            arow[lane + 32] = p1;
            __nv_bfloat16 h0 = __float2bfloat16(p0);
            __nv_bfloat16 h1 = __float2bfloat16(p1);
            Ph[row * 72 + lane] = h0;
            Ph[row * 72 + lane + 32] = h1;
            Pl[row * 72 + lane] = __float2bfloat16(p0 - __bfloat162float(h0));
            Pl[row * 72 + lane + 32] = __float2bfloat16(p1 - __bfloat162float(h1));
        }
        CP_WAIT0();          // V tile kt ready
        __syncthreads();     // + Ph/Pl visible
        if (kt < 31) {
            prefetch_pair(0, Khi, Klo, kt + 1);    // K prefetch overlaps AV MMA
            CP_COMMIT();
        }

        const __nv_bfloat16* Vh = (const __nv_bfloat16*)(smraw + A_KV + 2 * A_ARR);
        const __nv_bfloat16* Vl = Vh + 64 * 72;
#pragma unroll
        for (int kk = 0; kk < 64; kk += 16) {
            wmma::fragment<wmma::matrix_a, 16, 16, 16, __nv_bfloat16, wmma::row_major> ah[2], al[2];
            wmma::fragment<wmma::matrix_b, 16, 16, 16, __nv_bfloat16, wmma::row_major> bh_, bl_;
#pragma unroll
            for (int i = 0; i < 2; i++) {
                wmma::load_matrix_sync(ah[i], Ph + (wm * 32 + i * 16) * 72 + kk, 72);
                wmma::load_matrix_sync(al[i], Pl + (wm * 32 + i * 16) * 72 + kk, 72);
            }
            wmma::load_matrix_sync(bh_, Vh + kk * 72 + wn * 16, 72);
            wmma::load_matrix_sync(bl_, Vl + kk * 72 + wn * 16, 72);
#pragma unroll
            for (int i = 0; i < 2; i++) {
                wmma::mma_sync(accO[i], ah[i], bh_, accO[i]);
                wmma::mma_sync(accO[i], ah[i], bl_, accO[i]);
                wmma::mma_sync(accO[i], al[i], bh_, accO[i]);
            }
        }
        __syncthreads();     // protect V buffer + Ph/Pl before next iteration
    }

    // epilogue: accO already normalized (p includes il) -> XH hi/lo
#pragma unroll
    for (int i = 0; i < 2; i++)
        wmma::store_matrix_sync(Sm + (wm * 32 + i * 16) * 68 + wn * 16, accO[i], 68, wmma::mem_row_major);
    __syncthreads();

    __nv_bfloat16* XHhi = (__nv_bfloat16*)(g_arena + xhhi_off);
    __nv_bfloat16* XHlo = (__nv_bfloat16*)(g_arena + xhlo_off);
#pragma unroll
    for (int i = 0; i < 16; i++) {
        int v = tid + 256 * i;
        int r = v >> 6, c = v & 63;
        float x = Sm[r * 68 + c];
        __nv_bfloat16 hh = __float2bfloat16(x);
        size_t g = ((size_t)b * S + q0 + r) * D + h * HD + c;
        XHhi[g] = hh;
        XHlo[g] = __float2bfloat16(x - __bfloat162float(hh));
    }
}

// ---------------- launch ----------------
extern "C" void kernel_launch(void* const* d_in, const int* in_sizes, int n_in,
                              void* d_out, int out_size)
{
    const float* query = (const float*)d_in[0];
    const float* key   = (const float*)d_in[1];
    const float* value = (const float*)d_in[2];
    const int*   mask  = (const int*)d_in[3];
    const float* Wq    = (const float*)d_in[4];
    const float* bq    = (const float*)d_in[5];
    const float* Wk    = (const float*)d_in[6];
    const float* bk    = (const float*)d_in[7];
    const float* Wv    = (const float*)d_in[8];
    const float* bv    = (const float*)d_in[9];
    const float* Wo    = (const float*)d_in[10];
    const float* bo    = (const float*)d_in[11];

    float* out_x = (float*)d_out;            // [B,S,D]
    float* attn  = out_x + NEL;              // [B,H,S,S]

    cudaFuncSetAttribute(gemm_kernel, cudaFuncAttributeMaxDynamicSharedMemorySize, GEMM_SMEM);
    cudaFuncSetAttribute(attn_fused_kernel, cudaFuncAttributeMaxDynamicSharedMemorySize, ATTN_SMEM);

    int nblk = (int)(NEL / 256);
    int wblk = (int)(WEL / 256);
    dim3 ggrid(D / 128, (B * S) / 128);   // (8, 32)

    split_kernel<<<wblk, 256>>>(Wq, OFF_W_HI + 0 * WEL * 2, OFF_W_LO + 0 * WEL * 2, (int)WEL);
    split_kernel<<<wblk, 256>>>(Wk, OFF_W_HI + 1 * WEL * 2, OFF_W_LO + 1 * WEL * 2, (int)WEL);
    split_kernel<<<wblk, 256>>>(Wv, OFF_W_HI + 2 * WEL * 2, OFF_W_LO + 2 * WEL * 2, (int)WEL);
    split_kernel<<<wblk, 256>>>(Wo, OFF_W_HI + 3 * WEL * 2, OFF_W_LO + 3 * WEL * 2, (int)WEL);
    split_kernel<<<nblk, 256>>>(query, OFF_IN_HI + 0 * NEL * 2, OFF_IN_LO + 0 * NEL * 2, (int)NEL);
    gemm_kernel<<<ggrid, 256, GEMM_SMEM>>>(OFF_IN_HI + 0 * NEL * 2, OFF_IN_LO + 0 * NEL * 2,
                                           OFF_W_HI + 0 * WEL * 2, OFF_W_LO + 0 * WEL * 2,
                                           bq, nullptr, OFF_QKV_HI + 0 * NEL * 2, OFF_QKV_LO + 0 * NEL * 2);
    split_kernel<<<nblk, 256>>>(key,   OFF_IN_HI + 1 * NEL * 2, OFF_IN_LO + 1 * NEL * 2, (int)NEL);
    gemm_kernel<<<ggrid, 256, GEMM_SMEM>>>(OFF_IN_HI + 1 * NEL * 2, OFF_IN_LO + 1 * NEL * 2,
                                           OFF_W_HI + 1 * WEL * 2, OFF_W_LO + 1 * WEL * 2,
                                           bk, nullptr, OFF_QKV_HI + 1 * NEL * 2, OFF_QKV_LO + 1 * NEL * 2);
    split_kernel<<<nblk, 256>>>(value, OFF_IN_HI + 2 * NEL * 2, OFF_IN_LO + 2 * NEL * 2, (int)NEL);
    gemm_kernel<<<ggrid, 256, GEMM_SMEM>>>(OFF_IN_HI + 2 * NEL * 2, OFF_IN_LO + 2 * NEL * 2,
                                           OFF_W_HI + 2 * WEL * 2, OFF_W_LO + 2 * WEL * 2,
                                           bv, nullptr, OFF_QKV_HI + 2 * NEL * 2, OFF_QKV_LO + 2 * NEL * 2);

    attn_fused_kernel<<<dim3(S / 64, B * H), 256, ATTN_SMEM>>>(
        OFF_QKV_HI + 0 * NEL * 2, OFF_QKV_LO + 0 * NEL * 2,
        OFF_QKV_HI + 1 * NEL * 2, OFF_QKV_LO + 1 * NEL * 2,
        OFF_QKV_HI + 2 * NEL * 2, OFF_QKV_LO + 2 * NEL * 2,
        mask, attn, OFF_XH_HI, OFF_XH_LO);

    gemm_kernel<<<ggrid, 256, GEMM_SMEM>>>(OFF_XH_HI, OFF_XH_LO,
                                           OFF_W_HI + 3 * WEL * 2, OFF_W_LO + 3 * WEL * 2,
                                           bo, out_x, 0, 0);
}

// round 11
// speedup vs baseline: 1.0838x; 1.0838x over previous
#include <cuda_runtime.h>
#include <cuda_bf16.h>
#include <mma.h>
#include <cstdint>

using namespace nvcuda;

// Problem constants
constexpr int B = 2, S = 2048, D = 1024, H = 16, HD = 64;
constexpr size_t NEL = (size_t)B * S * D;   // 4194304
constexpr size_t WEL = (size_t)D * D;       // 1048576

// ---------------- scratch arena ----------------
constexpr size_t OFF_IN_HI  = 0;
constexpr size_t OFF_IN_LO  = OFF_IN_HI  + 3 * NEL * 2;
constexpr size_t OFF_W_HI   = OFF_IN_LO  + 3 * NEL * 2;
constexpr size_t OFF_W_LO   = OFF_W_HI   + 4 * WEL * 2;
constexpr size_t OFF_QKV_HI = OFF_W_LO   + 4 * WEL * 2;
constexpr size_t OFF_QKV_LO = OFF_QKV_HI + 3 * NEL * 2;
constexpr size_t OFF_XH_HI  = OFF_QKV_LO + 3 * NEL * 2;
constexpr size_t OFF_XH_LO  = OFF_XH_HI  + NEL * 2;
constexpr size_t ARENA_BYTES = OFF_XH_LO + NEL * 2;

__device__ __align__(256) unsigned char g_arena[ARENA_BYTES];

#define CP_ASYNC16(dst, src) asm volatile("cp.async.cg.shared.global [%0], [%1], 16;\n" :: "r"(dst), "l"(src))
#define CP_COMMIT()  asm volatile("cp.async.commit_group;\n" ::: "memory")
#define CP_WAIT1()   asm volatile("cp.async.wait_group 1;\n" ::: "memory")

struct Ptrs4 { const float* p[4]; };

// ---------------- split fp32 -> bf16 hi/lo (multi-tensor, grid.y selects) ----
__global__ void split_multi_kernel(Ptrs4 srcs, size_t hi0, size_t lo0,
                                   size_t stride_bytes, int n)
{
    int z = blockIdx.y;
    int i = blockIdx.x * blockDim.x + threadIdx.x;
    if (i >= n) return;
    const float* src = srcs.p[z];
    __nv_bfloat16* hi = (__nv_bfloat16*)(g_arena + hi0 + z * stride_bytes);
    __nv_bfloat16* lo = (__nv_bfloat16*)(g_arena + lo0 + z * stride_bytes);
    float x = src[i];
    __nv_bfloat16 h = __float2bfloat16(x);
    hi[i] = h;
    lo[i] = __float2bfloat16(x - __bfloat162float(h));
}

// ---------------- GEMM: 128x128 CTA tile, 2-stage, warp tile 64x32 ----------
// grid.z selects tensor triple: A = ahi0 + z*stride_a, W = whi0 + z*stride_w,
// dst = hi0/lo0 + z*stride_a (or cext fp32 when non-null). Bias chosen by z.
constexpr int G_ARR = 128 * 40 * 2;
constexpr int G_STG = 4 * G_ARR;
constexpr int GEMM_SMEM = 2 * G_STG;         // 81920

__global__ __launch_bounds__(256, 2) void gemm_kernel(
    size_t ahi0, size_t alo0, size_t whi0, size_t wlo0,
    size_t stride_a, size_t stride_w,
    const float* b0, const float* b1, const float* b2,
    float* __restrict__ cext, size_t hi0, size_t lo0)
{
    int z = blockIdx.z;
    const float* bias = (z == 0) ? b0 : ((z == 1) ? b1 : b2);
    const __nv_bfloat16* Ahi = (const __nv_bfloat16*)(g_arena + ahi0 + z * stride_a);
    const __nv_bfloat16* Alo = (const __nv_bfloat16*)(g_arena + alo0 + z * stride_a);
    const __nv_bfloat16* Whi = (const __nv_bfloat16*)(g_arena + whi0 + z * stride_w);
    const __nv_bfloat16* Wlo = (const __nv_bfloat16*)(g_arena + wlo0 + z * stride_w);

    extern __shared__ unsigned char smraw[];

    int m0 = blockIdx.y * 128, n0 = blockIdx.x * 128;
    int tid = threadIdx.x, wid = tid >> 5;
    int wm = wid & 1, wn = wid >> 1;          // warp tile 64(m) x 32(n)

    auto fill = [&](int st, int kt) {
        int k0 = kt * 32;
        __nv_bfloat16* Ah = (__nv_bfloat16*)(smraw + st * G_STG);
        __nv_bfloat16* Al = (__nv_bfloat16*)(smraw + st * G_STG + G_ARR);
        __nv_bfloat16* Bh = (__nv_bfloat16*)(smraw + st * G_STG + 2 * G_ARR);
        __nv_bfloat16* Bl = (__nv_bfloat16*)(smraw + st * G_STG + 3 * G_ARR);
#pragma unroll
        for (int i = 0; i < 2; i++) {
            int v = tid + 256 * i;
            int r = v >> 2, c = (v & 3) * 8;
            size_t ga = (size_t)(m0 + r) * D + k0 + c;
            size_t gb = (size_t)(n0 + r) * D + k0 + c;
            CP_ASYNC16((unsigned)__cvta_generic_to_shared(Ah + r * 40 + c), Ahi + ga);
            CP_ASYNC16((unsigned)__cvta_generic_to_shared(Al + r * 40 + c), Alo + ga);
            CP_ASYNC16((unsigned)__cvta_generic_to_shared(Bh + r * 40 + c), Whi + gb);
            CP_ASYNC16((unsigned)__cvta_generic_to_shared(Bl + r * 40 + c), Wlo + gb);
        }
    };

    wmma::fragment<wmma::accumulator, 16, 16, 16, float> acc[4][2];
#pragma unroll
    for (int i = 0; i < 4; i++)
#pragma unroll
        for (int j = 0; j < 2; j++) wmma::fill_fragment(acc[i][j], 0.0f);

    fill(0, 0); CP_COMMIT();
    for (int kt = 0; kt < 32; kt++) {
        if (kt < 31) fill((kt + 1) & 1, kt + 1);
        CP_COMMIT();
        CP_WAIT1();
        __syncthreads();
        int st = kt & 1;
        const __nv_bfloat16* Ah = (const __nv_bfloat16*)(smraw + st * G_STG);
        const __nv_bfloat16* Al = (const __nv_bfloat16*)(smraw + st * G_STG + G_ARR);
        const __nv_bfloat16* Bh = (const __nv_bfloat16*)(smraw + st * G_STG + 2 * G_ARR);
        const __nv_bfloat16* Bl = (const __nv_bfloat16*)(smraw + st * G_STG + 3 * G_ARR);
#pragma unroll
        for (int kk = 0; kk < 32; kk += 16) {
            wmma::fragment<wmma::matrix_a, 16, 16, 16, __nv_bfloat16, wmma::row_major> ah[4], al[4];
#pragma unroll
            for (int i = 0; i < 4; i++) {
                wmma::load_matrix_sync(ah[i], Ah + (wm * 64 + i * 16) * 40 + kk, 40);
                wmma::load_matrix_sync(al[i], Al + (wm * 64 + i * 16) * 40 + kk, 40);
            }
#pragma unroll
            for (int j = 0; j < 2; j++) {
                wmma::fragment<wmma::matrix_b, 16, 16, 16, __nv_bfloat16, wmma::col_major> bh, bl;
                wmma::load_matrix_sync(bh, Bh + (wn * 32 + j * 16) * 40 + kk, 40);
                wmma::load_matrix_sync(bl, Bl + (wn * 32 + j * 16) * 40 + kk, 40);
#pragma unroll
                for (int i = 0; i < 4; i++) {
                    wmma::mma_sync(acc[i][j], ah[i], bh, acc[i][j]);
                    wmma::mma_sync(acc[i][j], ah[i], bl, acc[i][j]);
                    wmma::mma_sync(acc[i][j], al[i], bh, acc[i][j]);
                }
            }
        }
        __syncthreads();
    }

    float* Cs = (float*)smraw;
    __nv_bfloat16* hi = (__nv_bfloat16*)(g_arena + hi0 + z * stride_a);
    __nv_bfloat16* lo = (__nv_bfloat16*)(g_arena + lo0 + z * stride_a);
#pragma unroll
    for (int half = 0; half < 2; half++) {
        __syncthreads();
        if (wm == half) {
#pragma unroll
            for (int i = 0; i < 4; i++)
#pragma unroll
                for (int j = 0; j < 2; j++)
                    wmma::store_matrix_sync(Cs + (i * 16) * 132 + wn * 32 + j * 16,
                                            acc[i][j], 132, wmma::mem_row_major);
        }
        __syncthreads();
#pragma unroll
        for (int i = 0; i < 32; i++) {
            int v = tid + 256 * i;
            int r = v >> 7, c = v & 127;
            float x = Cs[r * 132 + c] + bias[n0 + c];
            size_t g = (size_t)(m0 + half * 64 + r) * D + n0 + c;
            if (cext) {
                cext[g] = x;
            } else {
                __nv_bfloat16 h = __float2bfloat16(x);
                hi[g] = h;
                lo[g] = __float2bfloat16(x - __bfloat162float(h));
            }
        }
    }
}

// ---------------- fused attention (R9 verbatim): two-pass, max-free stats ----
constexpr int A_Q   = 0;
constexpr int A_QL  = A_Q  + 64 * 72 * 2;
constexpr int A_KVH = A_QL + 64 * 72 * 2;
constexpr int A_KVL = A_KVH + 2 * 64 * 72 * 2;
constexpr int A_S   = A_KVL + 2 * 64 * 72 * 2;   // Sm[64][68] f32
constexpr int A_PH  = A_S  + 64 * 68 * 4;
constexpr int A_PL  = A_PH + 64 * 72 * 2;
constexpr int A_L   = A_PL + 64 * 72 * 2;        // lrowinv[64]
constexpr int ATTN_SMEM = A_L + 64 * 4;

__global__ __launch_bounds__(256) void attn_fused_kernel(
    size_t qhi_off, size_t qlo_off, size_t khi_off, size_t klo_off,
    size_t vhi_off, size_t vlo_off,
    const int* __restrict__ mask, float* __restrict__ attn,
    size_t xhhi_off, size_t xhlo_off)
{
    extern __shared__ unsigned char smraw[];
    __nv_bfloat16* Qh  = (__nv_bfloat16*)(smraw + A_Q);
    __nv_bfloat16* Ql  = (__nv_bfloat16*)(smraw + A_QL);
    __nv_bfloat16* KVh = (__nv_bfloat16*)(smraw + A_KVH);
    __nv_bfloat16* KVl = (__nv_bfloat16*)(smraw + A_KVL);
    float*         Sm  = (float*)(smraw + A_S);
    __nv_bfloat16* Ph  = (__nv_bfloat16*)(smraw + A_PH);
    __nv_bfloat16* Pl  = (__nv_bfloat16*)(smraw + A_PL);
    float*         lrowinv = (float*)(smraw + A_L);

    const __nv_bfloat16* Qhi = (const __nv_bfloat16*)(g_arena + qhi_off);
    const __nv_bfloat16* Qlo = (const __nv_bfloat16*)(g_arena + qlo_off);
    const __nv_bfloat16* Khi = (const __nv_bfloat16*)(g_arena + khi_off);
    const __nv_bfloat16* Klo = (const __nv_bfloat16*)(g_arena + klo_off);
    const __nv_bfloat16* Vhi = (const __nv_bfloat16*)(g_arena + vhi_off);
    const __nv_bfloat16* Vlo = (const __nv_bfloat16*)(g_arena + vlo_off);

    int bh = blockIdx.y;
    int b = bh >> 4, h = bh & 15;
    int q0 = blockIdx.x * 64;
    int tid = threadIdx.x, wid = tid >> 5, lane = tid & 31;
    int wm = wid & 1, wn = wid >> 1;

    auto prefetch_kv = [&](int st, const __nv_bfloat16* srch, const __nv_bfloat16* srcl, int kt) {
        size_t gbase = ((size_t)b * S + kt * 64) * D + h * HD;
#pragma unroll
        for (int i = 0; i < 2; i++) {
            int v = tid + 256 * i;
            int r = v >> 3, c = (v & 7) * 8;
            size_t g = gbase + (size_t)r * D + c;
            CP_ASYNC16((unsigned)__cvta_generic_to_shared(KVh + (st * 64 + r) * 72 + c), srch + g);
            CP_ASYNC16((unsigned)__cvta_generic_to_shared(KVl + (st * 64 + r) * 72 + c), srcl + g);
        }
    };

    size_t qbase = ((size_t)b * S + q0) * D + h * HD;
#pragma unroll
    for (int i = 0; i < 4; i++) {
        int v = tid + 256 * i;
        int r = v >> 4, c = (v & 15) * 4;
        *(uint2*)&Qh[r * 72 + c] = *(const uint2*)(Qhi + qbase + (size_t)r * D + c);
        *(uint2*)&Ql[r * 72 + c] = *(const uint2*)(Qlo + qbase + (size_t)r * D + c);
    }
    __syncthreads();

    // ---------- pass 1: scores (staged raw) + max-free sum stats ----------
    float tsum[8];
#pragma unroll
    for (int i = 0; i < 8; i++) tsum[i] = 0.0f;

    prefetch_kv(0, Khi, Klo, 0);
    CP_COMMIT();
    for (int kt = 0; kt < 32; kt++) {
        if (kt < 31) prefetch_kv((kt + 1) & 1, Khi, Klo, kt + 1);
        CP_COMMIT();
        CP_WAIT1();
        __syncthreads();
        int st = kt & 1;

        wmma::fragment<wmma::accumulator, 16, 16, 16, float> acc[2];
        wmma::fill_fragment(acc[0], 0.0f);
        wmma::fill_fragment(acc[1], 0.0f);
#pragma unroll
        for (int kk = 0; kk < HD; kk += 16) {
            wmma::fragment<wmma::matrix_a, 16, 16, 16, __nv_bfloat16, wmma::row_major> ah[2], al[2];
            wmma::fragment<wmma::matrix_b, 16, 16, 16, __nv_bfloat16, wmma::col_major> bh_, bl_;
#pragma unroll
            for (int i = 0; i < 2; i++) {
                wmma::load_matrix_sync(ah[i], Qh + (wm * 32 + i * 16) * 72 + kk, 72);
                wmma::load_matrix_sync(al[i], Ql + (wm * 32 + i * 16) * 72 + kk, 72);
            }
            wmma::load_matrix_sync(bh_, KVh + (st * 64 + wn * 16) * 72 + kk, 72);
            wmma::load_matrix_sync(bl_, KVl + (st * 64 + wn * 16) * 72 + kk, 72);
#pragma unroll
            for (int i = 0; i < 2; i++) {
                wmma::mma_sync(acc[i], ah[i], bh_, acc[i]);
                wmma::mma_sync(acc[i], ah[i], bl_, acc[i]);
                wmma::mma_sync(acc[i], al[i], bh_, acc[i]);
            }
        }
#pragma unroll
        for (int i = 0; i < 2; i++) {
            for (int t = 0; t < acc[i].num_elements; t++) acc[i].x[t] *= 0.125f;
            wmma::store_matrix_sync(Sm + (wm * 32 + i * 16) * 68 + wn * 16, acc[i], 68, wmma::mem_row_major);
        }
        __syncthreads();

        int colb = kt * 64;
        const int* mk = mask + (size_t)b * S + colb;
        int mv0 = mk[lane], mv1 = mk[lane + 32];
#pragma unroll
        for (int r8 = 0; r8 < 8; r8++) {
            int row = wid * 8 + r8;
            float s0 = Sm[row * 68 + lane];        if (mv0 == 0) s0 = -1e9f;
            float s1 = Sm[row * 68 + lane + 32];   if (mv1 == 0) s1 = -1e9f;
            float* arow = attn + ((size_t)bh * S + q0 + row) * S + colb;
            arow[lane] = s0;
            arow[lane + 32] = s1;
            tsum[r8] += __expf(s0) + __expf(s1);
        }
        __syncthreads();
    }

    // merge row sums, store 1/l
#pragma unroll
    for (int r8 = 0; r8 < 8; r8++) {
        float s = tsum[r8];
#pragma unroll
        for (int o = 16; o; o >>= 1) s += __shfl_xor_sync(0xffffffffu, s, o);
        if (lane == 0) lrowinv[wid * 8 + r8] = 1.0f / s;
    }
    __syncthreads();

    // ---------- pass 2: p = exp(s)*il, write attn, split p, AV ----------
    wmma::fragment<wmma::accumulator, 16, 16, 16, float> accO[2];
    wmma::fill_fragment(accO[0], 0.0f);
    wmma::fill_fragment(accO[1], 0.0f);

    prefetch_kv(0, Vhi, Vlo, 0);
    CP_COMMIT();
    for (int kt = 0; kt < 32; kt++) {
        if (kt < 31) prefetch_kv((kt + 1) & 1, Vhi, Vlo, kt + 1);
        CP_COMMIT();
        CP_WAIT1();
        __syncthreads();
        int st = kt & 1, colb = kt * 64;

#pragma unroll
        for (int r8 = 0; r8 < 8; r8++) {
            int row = wid * 8 + r8;
            float* arow = attn + ((size_t)bh * S + q0 + row) * S + colb;
            float il = lrowinv[row];
            float p0 = __expf(arow[lane]) * il;
            float p1 = __expf(arow[lane + 32]) * il;
            arow[lane] = p0;
            arow[lane + 32] = p1;
            __nv_bfloat16 h0 = __float2bfloat16(p0);
            __nv_bfloat16 h1 = __float2bfloat16(p1);
            Ph[row * 72 + lane] = h0;
            Ph[row * 72 + lane + 32] = h1;
            Pl[row * 72 + lane] = __float2bfloat16(p0 - __bfloat162float(h0));
            Pl[row * 72 + lane + 32] = __float2bfloat16(p1 - __bfloat162float(h1));
        }
        __syncthreads();

#pragma unroll
        for (int kk = 0; kk < 64; kk += 16) {
            wmma::fragment<wmma::matrix_a, 16, 16, 16, __nv_bfloat16, wmma::row_major> ah[2], al[2];
            wmma::fragment<wmma::matrix_b, 16, 16, 16, __nv_bfloat16, wmma::row_major> bh_, bl_;
#pragma unroll
            for (int i = 0; i < 2; i++) {
                wmma::load_matrix_sync(ah[i], Ph + (wm * 32 + i * 16) * 72 + kk, 72);
                wmma::load_matrix_sync(al[i], Pl + (wm * 32 + i * 16) * 72 + kk, 72);
            }
            wmma::load_matrix_sync(bh_, KVh + (st * 64 + kk) * 72 + wn * 16, 72);
            wmma::load_matrix_sync(bl_, KVl + (st * 64 + kk) * 72 + wn * 16, 72);
#pragma unroll
            for (int i = 0; i < 2; i++) {
                wmma::mma_sync(accO[i], ah[i], bh_, accO[i]);
                wmma::mma_sync(accO[i], ah[i], bl_, accO[i]);
                wmma::mma_sync(accO[i], al[i], bh_, accO[i]);
            }
        }
        __syncthreads();
    }

    // epilogue: accO already normalized -> XH hi/lo
#pragma unroll
    for (int i = 0; i < 2; i++)
        wmma::store_matrix_sync(Sm + (wm * 32 + i * 16) * 68 + wn * 16, accO[i], 68, wmma::mem_row_major);
    __syncthreads();

    __nv_bfloat16* XHhi = (__nv_bfloat16*)(g_arena + xhhi_off);
    __nv_bfloat16* XHlo = (__nv_bfloat16*)(g_arena + xhlo_off);
#pragma unroll
    for (int i = 0; i < 16; i++) {
        int v = tid + 256 * i;
        int r = v >> 6, c = v & 63;
        float x = Sm[r * 68 + c];
        __nv_bfloat16 hh = __float2bfloat16(x);
        size_t g = ((size_t)b * S + q0 + r) * D + h * HD + c;
        XHhi[g] = hh;
        XHlo[g] = __float2bfloat16(x - __bfloat162float(hh));
    }
}

// ---------------- launch ----------------
extern "C" void kernel_launch(void* const* d_in, const int* in_sizes, int n_in,
                              void* d_out, int out_size)
{
    const float* query = (const float*)d_in[0];
    const float* key   = (const float*)d_in[1];
    const float* value = (const float*)d_in[2];
    const int*   mask  = (const int*)d_in[3];
    const float* Wq    = (const float*)d_in[4];
    const float* bq    = (const float*)d_in[5];
    const float* Wk    = (const float*)d_in[6];
    const float* bk    = (const float*)d_in[7];
    const float* Wv    = (const float*)d_in[8];
    const float* bv    = (const float*)d_in[9];
    const float* Wo    = (const float*)d_in[10];
    const float* bo    = (const float*)d_in[11];

    float* out_x = (float*)d_out;            // [B,S,D]
    float* attn  = out_x + NEL;              // [B,H,S,S]

    cudaFuncSetAttribute(gemm_kernel, cudaFuncAttributeMaxDynamicSharedMemorySize, GEMM_SMEM);
    cudaFuncSetAttribute(attn_fused_kernel, cudaFuncAttributeMaxDynamicSharedMemorySize, ATTN_SMEM);

    // launch 1: split all 4 weights (grid.y selects)
    Ptrs4 wsrc; wsrc.p[0] = Wq; wsrc.p[1] = Wk; wsrc.p[2] = Wv; wsrc.p[3] = Wo;
    split_multi_kernel<<<dim3((unsigned)(WEL / 256), 4), 256>>>(
        wsrc, OFF_W_HI, OFF_W_LO, WEL * 2, (int)WEL);

    // launch 2: split all 3 inputs
    Ptrs4 isrc; isrc.p[0] = query; isrc.p[1] = key; isrc.p[2] = value; isrc.p[3] = nullptr;
    split_multi_kernel<<<dim3((unsigned)(NEL / 256), 3), 256>>>(
        isrc, OFF_IN_HI, OFF_IN_LO, NEL * 2, (int)NEL);

    // launch 3: QKV projections fused into one grid (z = 0,1,2)
    dim3 qkvgrid(D / 128, (B * S) / 128, 3);   // (8, 32, 3) = 768 CTAs
    gemm_kernel<<<qkvgrid, 256, GEMM_SMEM>>>(
        OFF_IN_HI, OFF_IN_LO, OFF_W_HI, OFF_W_LO,
        NEL * 2, WEL * 2,
        bq, bk, bv,
        nullptr, OFF_QKV_HI, OFF_QKV_LO);

    // launch 4: fused attention
    attn_fused_kernel<<<dim3(S / 64, B * H), 256, ATTN_SMEM>>>(
        OFF_QKV_HI + 0 * NEL * 2, OFF_QKV_LO + 0 * NEL * 2,
        OFF_QKV_HI + 1 * NEL * 2, OFF_QKV_LO + 1 * NEL * 2,
        OFF_QKV_HI + 2 * NEL * 2, OFF_QKV_LO + 2 * NEL * 2,
        mask, attn, OFF_XH_HI, OFF_XH_LO);

    // launch 5: output projection (z = 0 only)
    dim3 ogrid(D / 128, (B * S) / 128, 1);
    gemm_kernel<<<ogrid, 256, GEMM_SMEM>>>(
        OFF_XH_HI, OFF_XH_LO, OFF_W_HI + 3 * WEL * 2, OFF_W_LO + 3 * WEL * 2,
        0, 0,
        bo, bo, bo,
        out_x, 0, 0);
}

// round 14
// speedup vs baseline: 1.1254x; 1.0384x over previous
#include <cuda_runtime.h>
#include <cuda_bf16.h>
#include <mma.h>
#include <cstdint>

using namespace nvcuda;

// Problem constants
constexpr int B = 2, S = 2048, D = 1024, H = 16, HD = 64;
constexpr size_t NEL = (size_t)B * S * D;   // 4194304
constexpr size_t WEL = (size_t)D * D;       // 1048576

// ---------------- scratch arena ----------------
constexpr size_t OFF_IN_HI  = 0;
constexpr size_t OFF_IN_LO  = OFF_IN_HI  + 3 * NEL * 2;
constexpr size_t OFF_W_HI   = OFF_IN_LO  + 3 * NEL * 2;
constexpr size_t OFF_W_LO   = OFF_W_HI   + 4 * WEL * 2;
constexpr size_t OFF_QKV_HI = OFF_W_LO   + 4 * WEL * 2;
constexpr size_t OFF_QKV_LO = OFF_QKV_HI + 3 * NEL * 2;
constexpr size_t OFF_XH_HI  = OFF_QKV_LO + 3 * NEL * 2;
constexpr size_t OFF_XH_LO  = OFF_XH_HI  + NEL * 2;
constexpr size_t ARENA_BYTES = OFF_XH_LO + NEL * 2;

__device__ __align__(256) unsigned char g_arena[ARENA_BYTES];

#define CP_ASYNC16(dst, src) asm volatile("cp.async.cg.shared.global [%0], [%1], 16;\n" :: "r"(dst), "l"(src))
#define CP_COMMIT()  asm volatile("cp.async.commit_group;\n" ::: "memory")
#define CP_WAIT1()   asm volatile("cp.async.wait_group 1;\n" ::: "memory")

struct Ptrs4 { const float* p[4]; };

// ---------------- split fp32 -> bf16 hi/lo (multi-tensor, grid.y selects) ----
__global__ void split_multi_kernel(Ptrs4 srcs, size_t hi0, size_t lo0,
                                   size_t stride_bytes, int n)
{
    int z = blockIdx.y;
    int i = blockIdx.x * blockDim.x + threadIdx.x;
    if (i >= n) return;
    const float* src = srcs.p[z];
    __nv_bfloat16* hi = (__nv_bfloat16*)(g_arena + hi0 + z * stride_bytes);
    __nv_bfloat16* lo = (__nv_bfloat16*)(g_arena + lo0 + z * stride_bytes);
    float x = src[i];
    __nv_bfloat16 h = __float2bfloat16(x);
    hi[i] = h;
    lo[i] = __float2bfloat16(x - __bfloat162float(h));
}

// ---------------- GEMM: 128x128 CTA tile, 2-stage, warp tile 64x32 ----------
constexpr int G_ARR = 128 * 40 * 2;
constexpr int G_STG = 4 * G_ARR;
constexpr int GEMM_SMEM = 2 * G_STG;         // 81920

__global__ __launch_bounds__(256, 2) void gemm_kernel(
    size_t ahi0, size_t alo0, size_t whi0, size_t wlo0,
    size_t stride_a, size_t stride_w,
    const float* b0, const float* b1, const float* b2,
    float* __restrict__ cext, size_t hi0, size_t lo0)
{
    int z = blockIdx.z;
    const float* bias = (z == 0) ? b0 : ((z == 1) ? b1 : b2);
    const __nv_bfloat16* Ahi = (const __nv_bfloat16*)(g_arena + ahi0 + z * stride_a);
    const __nv_bfloat16* Alo = (const __nv_bfloat16*)(g_arena + alo0 + z * stride_a);
    const __nv_bfloat16* Whi = (const __nv_bfloat16*)(g_arena + whi0 + z * stride_w);
    const __nv_bfloat16* Wlo = (const __nv_bfloat16*)(g_arena + wlo0 + z * stride_w);

    extern __shared__ unsigned char smraw[];

    int m0 = blockIdx.y * 128, n0 = blockIdx.x * 128;
    int tid = threadIdx.x, wid = tid >> 5;
    int wm = wid & 1, wn = wid >> 1;          // warp tile 64(m) x 32(n)

    auto fill = [&](int st, int kt) {
        int k0 = kt * 32;
        __nv_bfloat16* Ah = (__nv_bfloat16*)(smraw + st * G_STG);
        __nv_bfloat16* Al = (__nv_bfloat16*)(smraw + st * G_STG + G_ARR);
        __nv_bfloat16* Bh = (__nv_bfloat16*)(smraw + st * G_STG + 2 * G_ARR);
        __nv_bfloat16* Bl = (__nv_bfloat16*)(smraw + st * G_STG + 3 * G_ARR);
#pragma unroll
        for (int i = 0; i < 2; i++) {
            int v = tid + 256 * i;
            int r = v >> 2, c = (v & 3) * 8;
            size_t ga = (size_t)(m0 + r) * D + k0 + c;
            size_t gb = (size_t)(n0 + r) * D + k0 + c;
            CP_ASYNC16((unsigned)__cvta_generic_to_shared(Ah + r * 40 + c), Ahi + ga);
            CP_ASYNC16((unsigned)__cvta_generic_to_shared(Al + r * 40 + c), Alo + ga);
            CP_ASYNC16((unsigned)__cvta_generic_to_shared(Bh + r * 40 + c), Whi + gb);
            CP_ASYNC16((unsigned)__cvta_generic_to_shared(Bl + r * 40 + c), Wlo + gb);
        }
    };

    wmma::fragment<wmma::accumulator, 16, 16, 16, float> acc[4][2];
#pragma unroll
    for (int i = 0; i < 4; i++)
#pragma unroll
        for (int j = 0; j < 2; j++) wmma::fill_fragment(acc[i][j], 0.0f);

    fill(0, 0); CP_COMMIT();
    for (int kt = 0; kt < 32; kt++) {
        if (kt < 31) fill((kt + 1) & 1, kt + 1);
        CP_COMMIT();
        CP_WAIT1();
        __syncthreads();
        int st = kt & 1;
        const __nv_bfloat16* Ah = (const __nv_bfloat16*)(smraw + st * G_STG);
        const __nv_bfloat16* Al = (const __nv_bfloat16*)(smraw + st * G_STG + G_ARR);
        const __nv_bfloat16* Bh = (const __nv_bfloat16*)(smraw + st * G_STG + 2 * G_ARR);
        const __nv_bfloat16* Bl = (const __nv_bfloat16*)(smraw + st * G_STG + 3 * G_ARR);
#pragma unroll
        for (int kk = 0; kk < 32; kk += 16) {
            wmma::fragment<wmma::matrix_a, 16, 16, 16, __nv_bfloat16, wmma::row_major> ah[4], al[4];
#pragma unroll
            for (int i = 0; i < 4; i++) {
                wmma::load_matrix_sync(ah[i], Ah + (wm * 64 + i * 16) * 40 + kk, 40);
                wmma::load_matrix_sync(al[i], Al + (wm * 64 + i * 16) * 40 + kk, 40);
            }
#pragma unroll
            for (int j = 0; j < 2; j++) {
                wmma::fragment<wmma::matrix_b, 16, 16, 16, __nv_bfloat16, wmma::col_major> bh, bl;
                wmma::load_matrix_sync(bh, Bh + (wn * 32 + j * 16) * 40 + kk, 40);
                wmma::load_matrix_sync(bl, Bl + (wn * 32 + j * 16) * 40 + kk, 40);
#pragma unroll
                for (int i = 0; i < 4; i++) {
                    wmma::mma_sync(acc[i][j], ah[i], bh, acc[i][j]);
                    wmma::mma_sync(acc[i][j], ah[i], bl, acc[i][j]);
                    wmma::mma_sync(acc[i][j], al[i], bh, acc[i][j]);
                }
            }
        }
        __syncthreads();
    }

    float* Cs = (float*)smraw;
    __nv_bfloat16* hi = (__nv_bfloat16*)(g_arena + hi0 + z * stride_a);
    __nv_bfloat16* lo = (__nv_bfloat16*)(g_arena + lo0 + z * stride_a);
#pragma unroll
    for (int half = 0; half < 2; half++) {
        __syncthreads();
        if (wm == half) {
#pragma unroll
            for (int i = 0; i < 4; i++)
#pragma unroll
                for (int j = 0; j < 2; j++)
                    wmma::store_matrix_sync(Cs + (i * 16) * 132 + wn * 32 + j * 16,
                                            acc[i][j], 132, wmma::mem_row_major);
        }
        __syncthreads();
#pragma unroll
        for (int i = 0; i < 32; i++) {
            int v = tid + 256 * i;
            int r = v >> 7, c = v & 127;
            float x = Cs[r * 132 + c] + bias[n0 + c];
            size_t g = (size_t)(m0 + half * 64 + r) * D + n0 + c;
            if (cext) {
                cext[g] = x;
            } else {
                __nv_bfloat16 h = __float2bfloat16(x);
                hi[g] = h;
                lo[g] = __float2bfloat16(x - __bfloat162float(h));
            }
        }
    }
}

// ---------------- fused attention: R9 structure, smem-aliased (74 KB) --------
// Sm (pass-1 scores / epilogue O staging) and Ph/Pl (pass-2 split P) share one
// region — they are never live at the same time.
constexpr int A_Q   = 0;
constexpr int A_QL  = A_Q  + 64 * 72 * 2;        //  9216
constexpr int A_KVH = A_QL + 64 * 72 * 2;        // 18432
constexpr int A_KVL = A_KVH + 2 * 64 * 72 * 2;   // 36864
constexpr int A_SP  = A_KVL + 2 * 64 * 72 * 2;   // 55296: union{Sm f32[64][68], Ph+Pl}
constexpr int A_SP_SZ = 2 * 64 * 72 * 2;         // 18432 >= 17408
constexpr int A_L   = A_SP + A_SP_SZ;            // 73728
constexpr int ATTN_SMEM = A_L + 64 * 4;          // 73984 -> up to 3 CTA/SM

__global__ __launch_bounds__(256, 3) void attn_fused_kernel(
    size_t qhi_off, size_t qlo_off, size_t khi_off, size_t klo_off,
    size_t vhi_off, size_t vlo_off,
    const int* __restrict__ mask, float* __restrict__ attn,
    size_t xhhi_off, size_t xhlo_off)
{
    extern __shared__ unsigned char smraw[];
    __nv_bfloat16* Qh  = (__nv_bfloat16*)(smraw + A_Q);
    __nv_bfloat16* Ql  = (__nv_bfloat16*)(smraw + A_QL);
    __nv_bfloat16* KVh = (__nv_bfloat16*)(smraw + A_KVH);
    __nv_bfloat16* KVl = (__nv_bfloat16*)(smraw + A_KVL);
    float*         Sm  = (float*)(smraw + A_SP);           // aliased
    __nv_bfloat16* Ph  = (__nv_bfloat16*)(smraw + A_SP);   // aliased
    __nv_bfloat16* Pl  = Ph + 64 * 72;
    float*         lrowinv = (float*)(smraw + A_L);

    const __nv_bfloat16* Qhi = (const __nv_bfloat16*)(g_arena + qhi_off);
    const __nv_bfloat16* Qlo = (const __nv_bfloat16*)(g_arena + qlo_off);
    const __nv_bfloat16* Khi = (const __nv_bfloat16*)(g_arena + khi_off);
    const __nv_bfloat16* Klo = (const __nv_bfloat16*)(g_arena + klo_off);
    const __nv_bfloat16* Vhi = (const __nv_bfloat16*)(g_arena + vhi_off);
    const __nv_bfloat16* Vlo = (const __nv_bfloat16*)(g_arena + vlo_off);

    int bh = blockIdx.y;
    int b = bh >> 4, h = bh & 15;
    int q0 = blockIdx.x * 64;
    int tid = threadIdx.x, wid = tid >> 5, lane = tid & 31;
    int wm = wid & 1, wn = wid >> 1;

    auto prefetch_kv = [&](int st, const __nv_bfloat16* srch, const __nv_bfloat16* srcl, int kt) {
        size_t gbase = ((size_t)b * S + kt * 64) * D + h * HD;
#pragma unroll
        for (int i = 0; i < 2; i++) {
            int v = tid + 256 * i;
            int r = v >> 3, c = (v & 7) * 8;
            size_t g = gbase + (size_t)r * D + c;
            CP_ASYNC16((unsigned)__cvta_generic_to_shared(KVh + (st * 64 + r) * 72 + c), srch + g);
            CP_ASYNC16((unsigned)__cvta_generic_to_shared(KVl + (st * 64 + r) * 72 + c), srcl + g);
        }
    };

    size_t qbase = ((size_t)b * S + q0) * D + h * HD;
#pragma unroll
    for (int i = 0; i < 4; i++) {
        int v = tid + 256 * i;
        int r = v >> 4, c = (v & 15) * 4;
        *(uint2*)&Qh[r * 72 + c] = *(const uint2*)(Qhi + qbase + (size_t)r * D + c);
        *(uint2*)&Ql[r * 72 + c] = *(const uint2*)(Qlo + qbase + (size_t)r * D + c);
    }
    __syncthreads();

    // ---------- pass 1: scores (staged raw) + max-free sum stats ----------
    float tsum[8];
#pragma unroll
    for (int i = 0; i < 8; i++) tsum[i] = 0.0f;

    prefetch_kv(0, Khi, Klo, 0);
    CP_COMMIT();
    for (int kt = 0; kt < 32; kt++) {
        if (kt < 31) prefetch_kv((kt + 1) & 1, Khi, Klo, kt + 1);
        CP_COMMIT();
        CP_WAIT1();
        __syncthreads();
        int st = kt & 1;

        wmma::fragment<wmma::accumulator, 16, 16, 16, float> acc[2];
        wmma::fill_fragment(acc[0], 0.0f);
        wmma::fill_fragment(acc[1], 0.0f);
#pragma unroll
        for (int kk = 0; kk < HD; kk += 16) {
            wmma::fragment<wmma::matrix_a, 16, 16, 16, __nv_bfloat16, wmma::row_major> ah[2], al[2];
            wmma::fragment<wmma::matrix_b, 16, 16, 16, __nv_bfloat16, wmma::col_major> bh_, bl_;
#pragma unroll
            for (int i = 0; i < 2; i++) {
                wmma::load_matrix_sync(ah[i], Qh + (wm * 32 + i * 16) * 72 + kk, 72);
                wmma::load_matrix_sync(al[i], Ql + (wm * 32 + i * 16) * 72 + kk, 72);
            }
            wmma::load_matrix_sync(bh_, KVh + (st * 64 + wn * 16) * 72 + kk, 72);
            wmma::load_matrix_sync(bl_, KVl + (st * 64 + wn * 16) * 72 + kk, 72);
#pragma unroll
            for (int i = 0; i < 2; i++) {
                wmma::mma_sync(acc[i], ah[i], bh_, acc[i]);
                wmma::mma_sync(acc[i], ah[i], bl_, acc[i]);
                wmma::mma_sync(acc[i], al[i], bh_, acc[i]);
            }
        }
#pragma unroll
        for (int i = 0; i < 2; i++) {
            for (int t = 0; t < acc[i].num_elements; t++) acc[i].x[t] *= 0.125f;
            wmma::store_matrix_sync(Sm + (wm * 32 + i * 16) * 68 + wn * 16, acc[i], 68, wmma::mem_row_major);
        }
        __syncthreads();

        int colb = kt * 64;
        const int* mk = mask + (size_t)b * S + colb;
        int mv0 = mk[lane], mv1 = mk[lane + 32];
#pragma unroll
        for (int r8 = 0; r8 < 8; r8++) {
            int row = wid * 8 + r8;
            float s0 = Sm[row * 68 + lane];        if (mv0 == 0) s0 = -1e9f;
            float s1 = Sm[row * 68 + lane + 32];   if (mv1 == 0) s1 = -1e9f;
            float* arow = attn + ((size_t)bh * S + q0 + row) * S + colb;
            arow[lane] = s0;
            arow[lane + 32] = s1;
            tsum[r8] += __expf(s0) + __expf(s1);
        }
        __syncthreads();
    }

    // merge row sums, store 1/l
#pragma unroll
    for (int r8 = 0; r8 < 8; r8++) {
        float s = tsum[r8];
#pragma unroll
        for (int o = 16; o; o >>= 1) s += __shfl_xor_sync(0xffffffffu, s, o);
        if (lane == 0) lrowinv[wid * 8 + r8] = 1.0f / s;
    }
    __syncthreads();

    // ---------- pass 2: p = exp(s)*il, write attn, split p, AV ----------
    wmma::fragment<wmma::accumulator, 16, 16, 16, float> accO[2];
    wmma::fill_fragment(accO[0], 0.0f);
    wmma::fill_fragment(accO[1], 0.0f);

    prefetch_kv(0, Vhi, Vlo, 0);
    CP_COMMIT();
    for (int kt = 0; kt < 32; kt++) {
        if (kt < 31) prefetch_kv((kt + 1) & 1, Vhi, Vlo, kt + 1);
        CP_COMMIT();
        CP_WAIT1();
        __syncthreads();
        int st = kt & 1, colb = kt * 64;

#pragma unroll
        for (int r8 = 0; r8 < 8; r8++) {
            int row = wid * 8 + r8;
            float* arow = attn + ((size_t)bh * S + q0 + row) * S + colb;
            float il = lrowinv[row];
            float p0 = __expf(arow[lane]) * il;
            float p1 = __expf(arow[lane + 32]) * il;
            arow[lane] = p0;
            arow[lane + 32] = p1;
            __nv_bfloat16 h0 = __float2bfloat16(p0);
            __nv_bfloat16 h1 = __float2bfloat16(p1);
            Ph[row * 72 + lane] = h0;
            Ph[row * 72 + lane + 32] = h1;
            Pl[row * 72 + lane] = __float2bfloat16(p0 - __bfloat162float(h0));
            Pl[row * 72 + lane + 32] = __float2bfloat16(p1 - __bfloat162float(h1));
        }
        __syncthreads();

#pragma unroll
        for (int kk = 0; kk < 64; kk += 16) {
            wmma::fragment<wmma::matrix_a, 16, 16, 16, __nv_bfloat16, wmma::row_major> ah[2], al[2];
            wmma::fragment<wmma::matrix_b, 16, 16, 16, __nv_bfloat16, wmma::row_major> bh_, bl_;
#pragma unroll
            for (int i = 0; i < 2; i++) {
                wmma::load_matrix_sync(ah[i], Ph + (wm * 32 + i * 16) * 72 + kk, 72);
                wmma::load_matrix_sync(al[i], Pl + (wm * 32 + i * 16) * 72 + kk, 72);
            }
            wmma::load_matrix_sync(bh_, KVh + (st * 64 + kk) * 72 + wn * 16, 72);
            wmma::load_matrix_sync(bl_, KVl + (st * 64 + kk) * 72 + wn * 16, 72);
#pragma unroll
            for (int i = 0; i < 2; i++) {
                wmma::mma_sync(accO[i], ah[i], bh_, accO[i]);
                wmma::mma_sync(accO[i], ah[i], bl_, accO[i]);
                wmma::mma_sync(accO[i], al[i], bh_, accO[i]);
            }
        }
        __syncthreads();
    }

    // epilogue: accO already normalized -> XH hi/lo (Sm region reused)
#pragma unroll
    for (int i = 0; i < 2; i++)
        wmma::store_matrix_sync(Sm + (wm * 32 + i * 16) * 68 + wn * 16, accO[i], 68, wmma::mem_row_major);
    __syncthreads();

    __nv_bfloat16* XHhi = (__nv_bfloat16*)(g_arena + xhhi_off);
    __nv_bfloat16* XHlo = (__nv_bfloat16*)(g_arena + xhlo_off);
#pragma unroll
    for (int i = 0; i < 16; i++) {
        int v = tid + 256 * i;
        int r = v >> 6, c = v & 63;
        float x = Sm[r * 68 + c];
        __nv_bfloat16 hh = __float2bfloat16(x);
        size_t g = ((size_t)b * S + q0 + r) * D + h * HD + c;
        XHhi[g] = hh;
        XHlo[g] = __float2bfloat16(x - __bfloat162float(hh));
    }
}

// ---------------- launch ----------------
extern "C" void kernel_launch(void* const* d_in, const int* in_sizes, int n_in,
                              void* d_out, int out_size)
{
    const float* query = (const float*)d_in[0];
    const float* key   = (const float*)d_in[1];
    const float* value = (const float*)d_in[2];
    const int*   mask  = (const int*)d_in[3];
    const float* Wq    = (const float*)d_in[4];
    const float* bq    = (const float*)d_in[5];
    const float* Wk    = (const float*)d_in[6];
    const float* bk    = (const float*)d_in[7];
    const float* Wv    = (const float*)d_in[8];
    const float* bv    = (const float*)d_in[9];
    const float* Wo    = (const float*)d_in[10];
    const float* bo    = (const float*)d_in[11];

    float* out_x = (float*)d_out;            // [B,S,D]
    float* attn  = out_x + NEL;              // [B,H,S,S]

    cudaFuncSetAttribute(gemm_kernel, cudaFuncAttributeMaxDynamicSharedMemorySize, GEMM_SMEM);
    cudaFuncSetAttribute(attn_fused_kernel, cudaFuncAttributeMaxDynamicSharedMemorySize, ATTN_SMEM);

    // launch 1: split all 4 weights
    Ptrs4 wsrc; wsrc.p[0] = Wq; wsrc.p[1] = Wk; wsrc.p[2] = Wv; wsrc.p[3] = Wo;
    split_multi_kernel<<<dim3((unsigned)(WEL / 256), 4), 256>>>(
        wsrc, OFF_W_HI, OFF_W_LO, WEL * 2, (int)WEL);

    // launch 2: split all 3 inputs
    Ptrs4 isrc; isrc.p[0] = query; isrc.p[1] = key; isrc.p[2] = value; isrc.p[3] = nullptr;
    split_multi_kernel<<<dim3((unsigned)(NEL / 256), 3), 256>>>(
        isrc, OFF_IN_HI, OFF_IN_LO, NEL * 2, (int)NEL);

    // launch 3: QKV projections (z = 0,1,2)
    dim3 qkvgrid(D / 128, (B * S) / 128, 3);
    gemm_kernel<<<qkvgrid, 256, GEMM_SMEM>>>(
        OFF_IN_HI, OFF_IN_LO, OFF_W_HI, OFF_W_LO,
        NEL * 2, WEL * 2,
        bq, bk, bv,
        nullptr, OFF_QKV_HI, OFF_QKV_LO);

    // launch 4: fused attention
    attn_fused_kernel<<<dim3(S / 64, B * H), 256, ATTN_SMEM>>>(
        OFF_QKV_HI + 0 * NEL * 2, OFF_QKV_LO + 0 * NEL * 2,
        OFF_QKV_HI + 1 * NEL * 2, OFF_QKV_LO + 1 * NEL * 2,
        OFF_QKV_HI + 2 * NEL * 2, OFF_QKV_LO + 2 * NEL * 2,
        mask, attn, OFF_XH_HI, OFF_XH_LO);

    // launch 5: output projection
    dim3 ogrid(D / 128, (B * S) / 128, 1);
    gemm_kernel<<<ogrid, 256, GEMM_SMEM>>>(
        OFF_XH_HI, OFF_XH_LO, OFF_W_HI + 3 * WEL * 2, OFF_W_LO + 3 * WEL * 2,
        0, 0,
        bo, bo, bo,
        out_x, 0, 0);
}